// round 1
// baseline (speedup 1.0000x reference)
#include <cuda_runtime.h>

// BPGNN: sparse belief propagation on a degree-16 circulant graph.
// N=4096 nodes, E=65536 directed edges, Eu=32768 upper edges, HID=64.

#define MAXN 4096
#define MAXE 65536

// ---- device scratch (no allocations allowed) ----
__device__ float  dJv[MAXE];          // J value per directed edge
__device__ float  dCij[MAXE];         // symmetric attention coefficient per edge
__device__ float  daJ[MAXE];          // Jv / Cij per edge
__device__ int    dRowStart[MAXN + 1];
__device__ float  dF1[MAXN], dF2[MAXN], dCi[MAXN], dDomInv[MAXN];
__device__ float2 dBx[MAXN];
__device__ float2 dEmA[MAXE], dEmB[MAXE];     // ping-pong edge messages (log domain)
__device__ float2 dHidA[MAXN], dHidB[MAXN];   // ping-pong node hidden (log beliefs)
__device__ double dAccNode, dAccEdge;
__device__ unsigned gBarCount;
__device__ volatile unsigned gBarGen;

__device__ __forceinline__ float lrelu02(float x) { return x < 0.f ? 0.2f * x : x; }

// ------------------------------------------------------------------
__global__ void kZero(int N, int E) {
    dAccNode = 0.0; dAccEdge = 0.0;
    gBarCount = 0u;
    dRowStart[N] = E;
}

// per edge: gather J value, mark CSR row starts (row[] is sorted)
__global__ void kEdgeGather(const float* __restrict__ J, const int* __restrict__ row,
                            const int* __restrict__ col, int N, int E) {
    int e = blockIdx.x * blockDim.x + threadIdx.x;
    if (e >= E) return;
    int r = row[e], c = col[e];
    dJv[e] = J[(size_t)r * (size_t)N + (size_t)c];
    if (e == 0 || row[e - 1] != r) dRowStart[r] = e;
}

// per node: features, GAT scalars f1/f2, Ci readout MLP (W2 staged in smem)
__global__ void kNodeFeat(const float* __restrict__ bias,
                          const float* __restrict__ gat_W, const float* __restrict__ gat_a,
                          const float* __restrict__ W1, const float* __restrict__ b1,
                          const float* __restrict__ W2, const float* __restrict__ b2,
                          const float* __restrict__ W3, const float* __restrict__ b3,
                          int N, float* __restrict__ outCi) {
    __shared__ float sW1[4 * 64];
    __shared__ float sb1[64];
    __shared__ float sW2[64 * 64];
    __shared__ float sb2[64];
    __shared__ float sW3[64];
    __shared__ float sb3;
    __shared__ float sWa[8];   // gat_W @ a1 (4), gat_W @ a2 (4)
    int tid = threadIdx.x;
    for (int idx = tid; idx < 4 * 64; idx += blockDim.x) sW1[idx] = W1[idx];
    for (int idx = tid; idx < 64 * 64; idx += blockDim.x) sW2[idx] = W2[idx];
    if (tid < 64) { sb1[tid] = b1[tid]; sb2[tid] = b2[tid]; sW3[tid] = W3[tid]; }
    if (tid == 0) sb3 = b3[0];
    if (tid < 8) {
        int c = tid & 3, half = tid >> 2;
        float acc = 0.f;
        for (int h = 0; h < 64; h++) acc += gat_W[c * 64 + h] * gat_a[half * 64 + h];
        sWa[tid] = acc;
    }
    __syncthreads();
    int i = blockIdx.x * blockDim.x + tid;
    if (i >= N) return;
    int base = dRowStart[i], deg = dRowStart[i + 1] - base;
    float js = 0.f;
    for (int s = 0; s < deg; s++) js += dJv[base + s];
    float feat[4];
    feat[0] = -bias[i]; feat[1] = bias[i]; feat[2] = (float)deg; feat[3] = js;
    float f1 = 0.f, f2 = 0.f;
#pragma unroll
    for (int c = 0; c < 4; c++) { f1 += feat[c] * sWa[c]; f2 += feat[c] * sWa[4 + c]; }
    dF1[i] = f1; dF2[i] = f2;
    float h1[64];
#pragma unroll
    for (int j = 0; j < 64; j++) {
        float a = sb1[j];
#pragma unroll
        for (int c = 0; c < 4; c++) a += feat[c] * sW1[c * 64 + j];
        h1[j] = fmaxf(a, 0.f);
    }
    float ci = sb3;
    for (int j = 0; j < 64; j++) {
        float a = sb2[j];
#pragma unroll
        for (int k = 0; k < 64; k++) a += h1[k] * sW2[k * 64 + j];
        ci += fmaxf(a, 0.f) * sW3[j];
    }
    dCi[i] = ci;
    outCi[i] = ci;
}

// per edge: Cij = 0.5*(exp(lrelu(f1_i+f2_j)) + exp(lrelu(f1_j+f2_i))), a = Jv/Cij
__global__ void kEdgeCij(const int* __restrict__ row, const int* __restrict__ col, int E) {
    int e = blockIdx.x * blockDim.x + threadIdx.x;
    if (e >= E) return;
    int r = row[e], c = col[e];
    float a1 = lrelu02(dF1[r] + dF2[c]);
    float a2 = lrelu02(dF1[c] + dF2[r]);
    float Cij = 0.5f * (expf(a1) + expf(a2));
    dCij[e] = Cij;
    daJ[e] = dJv[e] / Cij;
}

// per node: dom (clamped), bias scaling, initial hidden (em0 = 0)
__global__ void kNodeDom(const float* __restrict__ bias, int N, float* __restrict__ outDom) {
    int i = blockIdx.x * blockDim.x + threadIdx.x;
    if (i >= N) return;
    int base = dRowStart[i], deg = dRowStart[i + 1] - base;
    float cs = 0.f;
    for (int s = 0; s < deg; s++) cs += dCij[base + s];
    float raw = dCi[i] + cs;
    float mag = fmaxf(fabsf(raw), 0.1f);
    float dom = (raw < 0.f) ? -mag : mag;
    outDom[i] = dom;
    dDomInv[i] = 1.f / dom;
    float bs = bias[i] / dom;
    float u0 = -bs, u1 = bs;
    float m = fmaxf(u0, u1);
    float ls = m + log1pf(expf(-fabsf(u0 - u1)));
    dBx[i] = make_float2(u0, u1);
    dHidA[i] = make_float2(u0 - ls, u1 - ls);
}

// software grid barrier (all blocks co-resident by construction: 128 blocks on 148 SMs)
__device__ __forceinline__ void gridBarrier() {
    __syncthreads();
    __threadfence();
    if (threadIdx.x == 0) {
        unsigned gen = gBarGen;
        if (atomicAdd(&gBarCount, 1u) == gridDim.x - 1u) {
            gBarCount = 0u;
            __threadfence();
            gBarGen = gen + 1u;
        } else {
            while (gBarGen == gen) __nanosleep(64);
        }
        __threadfence();
    }
    __syncthreads();
}

// Persistent BP loop: thread t owns outgoing edge slot s of node j (j = t/16).
// Per step it computes em_new for the REVERSE (incoming) edge rev[e] and the
// 16 lanes of a node reduce those immediately into hidden_new[j].
// lnZ cancels analytically and is never computed.
__global__ void __launch_bounds__(512, 1)
kBP(const int* __restrict__ col, const int* __restrict__ rev,
    const int* __restrict__ nstepPtr, int N) {
    int t = blockIdx.x * blockDim.x + threadIdx.x;
    int j = t >> 4, s = t & 15;
    bool valid = false;
    int e = 0, k = 0, f = 0;
    float a = 0.f, C = 0.f, dinv = 0.f;
    float2 bx = make_float2(0.f, 0.f);
    if (j < N) {
        int base = dRowStart[j];
        int deg = dRowStart[j + 1] - base;
        if (s < deg) {
            valid = true;
            e = base + s;
            k = col[e]; f = rev[e];
            a = daJ[e]; C = dCij[e];           // symmetric: same on e and rev[e]
            bx = dBx[j]; dinv = dDomInv[j];
            dEmA[e] = make_float2(0.f, 0.f);   // em0 = log(1) = 0 (self-read only)
        }
    }
    int nstep = *nstepPtr;
    float2* emCur = dEmA;  float2* emNext = dEmB;
    float2* hidCur = dHidA; float2* hidNext = dHidB;
    for (int it = 0; it < nstep; ++it) {
        float2 emn = make_float2(0.f, 0.f);
        if (valid) {
            float2 hk = hidCur[k];             // hidden of neighbor (source of incoming edge)
            float2 mu = emCur[e];              // own outgoing em = reverse message for edge f
            float p = hk.x - mu.x, q = hk.y - mu.y;
            float t0 = fmaxf(p + a, q - a);    // max_a of log M column b=0
            float t1 = fmaxf(p - a, q + a);    // column b=1
            float m = fmaxf(t0, t1);
            float ls = m + log1pf(expf(-fabsf(t0 - t1)));   // log sum_b exp(tb*)
            emn.x = C * (t0 - ls);
            emn.y = C * (t1 - ls);
            emNext[f] = emn;                   // incoming edge of node j
        }
#pragma unroll
        for (int o = 8; o > 0; o >>= 1) {      // sum over the 16 incoming edges of node j
            emn.x += __shfl_xor_sync(0xffffffffu, emn.x, o);
            emn.y += __shfl_xor_sync(0xffffffffu, emn.y, o);
        }
        if (valid && s == 0) {
            float u0 = bx.x + emn.x * dinv;
            float u1 = bx.y + emn.y * dinv;
            float m2 = fmaxf(u0, u1);
            float ls2 = m2 + log1pf(expf(-fabsf(u0 - u1)));
            hidNext[j] = make_float2(u0 - ls2, u1 - ls2);
        }
        gridBarrier();
        float2* tmp = emCur; emCur = emNext; emNext = tmp;
        tmp = hidCur; hidCur = hidNext; hidNext = tmp;
    }
}

// node readout + node entropy (double atomic accumulation)
__global__ void kNodeOut(const int* __restrict__ nstepPtr, int N, float* __restrict__ out) {
    int i = blockIdx.x * blockDim.x + threadIdx.x;
    if (i >= N) return;
    const float2* hidF = ((*nstepPtr) & 1) ? dHidB : dHidA;
    float2 h = hidF[i];
    float r0 = expf(h.x), r1 = expf(h.y);
    out[2 * i] = r0; out[2 * i + 1] = r1;
    float nh = -(r0 * logf(r0 + 1e-16f) + r1 * logf(r1 + 1e-16f));
    atomicAdd(&dAccNode, (double)(dCi[i] * nh));
}

// pairwise readout per upper edge + edge entropy
__global__ void kEdgeOut(const int* __restrict__ nstepPtr, const int* __restrict__ ru,
                         const int* __restrict__ cu, const int* __restrict__ u2e,
                         const int* __restrict__ rev, int Eu,
                         float* __restrict__ outPw, float* __restrict__ outCu) {
    int u = blockIdx.x * blockDim.x + threadIdx.x;
    if (u >= Eu) return;
    int parity = (*nstepPtr) & 1;
    const float2* emF = parity ? dEmB : dEmA;
    const float2* hidF = parity ? dHidB : dHidA;
    int e = u2e[u];
    int f = rev[e];
    float Js = daJ[e];
    float2 hc = hidF[cu[u]], hr = hidF[ru[u]];
    float2 me = emF[e], mf = emF[f];
    float ti0 = hc.x - me.x, ti1 = hc.y - me.y;   // temp_i (index b)
    float tj0 = hr.x - mf.x, tj1 = hr.y - mf.y;   // temp_j (index a)
    float s00 = Js + ti0 + tj0;
    float s01 = -Js + ti1 + tj0;
    float s10 = -Js + ti0 + tj1;
    float s11 = Js + ti1 + tj1;
    float m = fmaxf(fmaxf(s00, s01), fmaxf(s10, s11));
    float p00 = expf(s00 - m), p01 = expf(s01 - m), p10 = expf(s10 - m), p11 = expf(s11 - m);
    float inv = 1.f / (p00 + p01 + p10 + p11);
    p00 *= inv; p01 *= inv; p10 *= inv; p11 *= inv;
    outPw[4 * u + 0] = p00; outPw[4 * u + 1] = p01;
    outPw[4 * u + 2] = p10; outPw[4 * u + 3] = p11;
    float Cu = dCij[e];
    outCu[u] = Cu;
    float eh = -(p00 * logf(p00 + 1e-16f) + p01 * logf(p01 + 1e-16f) +
                 p10 * logf(p10 + 1e-16f) + p11 * logf(p11 + 1e-16f));
    atomicAdd(&dAccEdge, (double)(Cu * eh));
}

__global__ void kScalars(float* __restrict__ outS) {
    outS[0] = (float)(dAccNode + dAccEdge);
    outS[1] = (float)dAccNode;
    outS[2] = (float)dAccEdge;
}

// ------------------------------------------------------------------
extern "C" void kernel_launch(void* const* d_in, const int* in_sizes, int n_in,
                              void* d_out, int out_size) {
    const float* J     = (const float*)d_in[0];
    const float* bias  = (const float*)d_in[1];
    const float* gat_W = (const float*)d_in[2];
    const float* gat_a = (const float*)d_in[3];
    const float* W1    = (const float*)d_in[4];
    const float* b1    = (const float*)d_in[5];
    const float* W2    = (const float*)d_in[6];
    const float* b2    = (const float*)d_in[7];
    const float* W3    = (const float*)d_in[8];
    const float* b3    = (const float*)d_in[9];
    const int*   row   = (const int*)d_in[10];
    const int*   col   = (const int*)d_in[11];
    const int*   rev   = (const int*)d_in[12];
    const int*   ru    = (const int*)d_in[13];
    const int*   cu    = (const int*)d_in[14];
    const int*   u2e   = (const int*)d_in[15];
    const int*   nstep = (const int*)d_in[16];
    (void)n_in; (void)out_size;

    int N  = in_sizes[1];
    int E  = in_sizes[10];
    int Eu = in_sizes[13];

    float* out = (float*)d_out;
    // output layout: readout[2N] | pairwise[4Eu] | 3 scalars | Ci[N] | Cij_u[Eu] | dom[N]
    int off_pw  = 2 * N;
    int off_sc  = off_pw + 4 * Eu;
    int off_Ci  = off_sc + 3;
    int off_Cu  = off_Ci + N;
    int off_dom = off_Cu + Eu;

    kZero<<<1, 1>>>(N, E);
    kEdgeGather<<<(E + 255) / 256, 256>>>(J, row, col, N, E);
    kNodeFeat<<<(N + 255) / 256, 256>>>(bias, gat_W, gat_a, W1, b1, W2, b2, W3, b3,
                                        N, out + off_Ci);
    kEdgeCij<<<(E + 255) / 256, 256>>>(row, col, E);
    kNodeDom<<<(N + 255) / 256, 256>>>(bias, N, out + off_dom);

    int slots = N * 16;                         // 16 edge slots per node
    int nblk = (slots + 511) / 512;             // 128 blocks -> co-resident on 148 SMs
    kBP<<<nblk, 512>>>(col, rev, nstep, N);

    kNodeOut<<<(N + 255) / 256, 256>>>(nstep, N, out);
    kEdgeOut<<<(Eu + 255) / 256, 256>>>(nstep, ru, cu, u2e, rev, Eu,
                                        out + off_pw, out + off_Cu);
    kScalars<<<1, 1>>>(out + off_sc);
}

// round 5
// speedup vs baseline: 2.1580x; 2.1580x over previous
#include <cuda_runtime.h>

// BPGNN fully fused: one persistent kernel, software grid barriers.
// N=4096 nodes, E=65536 directed edges (deg 16), Eu=32768, HID=64.

#define MAXN 4096
#define MAXE 65536
#define NB 128
#define NT 512

__device__ float  dJv[MAXE];
__device__ float  dCij[MAXE];
__device__ float  daJ[MAXE];
__device__ int    dRowStart[MAXN + 1];
__device__ float  dF1[MAXN], dF2[MAXN], dCi[MAXN];
__device__ float2 dEmA[MAXE], dEmB[MAXE];
__device__ float2 dHidA[MAXN], dHidB[MAXN];
__device__ double dAccNode, dAccEdge;
__device__ unsigned gBarCount;
__device__ volatile unsigned gBarGen;

__device__ __forceinline__ float lrelu02(float x) { return x < 0.f ? 0.2f * x : x; }

// L2 (coherent) loads for data written by other blocks
__device__ __forceinline__ float2 ldcg2(const float2* p) { return __ldcg(p); }
__device__ __forceinline__ float  ldcg1(const float* p)  { return __ldcg(p); }
__device__ __forceinline__ int    ldcgi(const int* p)    { return __ldcg(p); }
__device__ __forceinline__ double ldcgd(const double* p) { return __ldcg(p); }

// grid-wide sense barrier; all NB blocks co-resident (128 blocks <= 148 SMs)
__device__ __forceinline__ void gridBarrier() {
    __threadfence();            // all threads: push own stores toward L2
    __syncthreads();
    if (threadIdx.x == 0) {
        unsigned gen = gBarGen;
        if (atomicAdd(&gBarCount, 1u) == NB - 1u) {
            gBarCount = 0u;
            __threadfence();
            gBarGen = gen + 1u;
        } else {
            while (gBarGen == gen) __nanosleep(32);
        }
    }
    __syncthreads();
    __threadfence();
}

__device__ __forceinline__ float grpSum16(float v) {
#pragma unroll
    for (int o = 8; o > 0; o >>= 1) v += __shfl_xor_sync(0xffffffffu, v, o);
    return v;
}

__global__ void __launch_bounds__(NT, 1)
kFused(const float* __restrict__ J, const float* __restrict__ bias,
       const float* __restrict__ gat_W, const float* __restrict__ gat_a,
       const float* __restrict__ W1, const float* __restrict__ b1,
       const float* __restrict__ W2, const float* __restrict__ b2,
       const float* __restrict__ W3, const float* __restrict__ b3,
       const int* __restrict__ row, const int* __restrict__ col,
       const int* __restrict__ rev, const int* __restrict__ ru,
       const int* __restrict__ cu, const int* __restrict__ u2e,
       const int* __restrict__ nstepPtr,
       int N, int E, int Eu,
       int offPw, int offSc, int offCi, int offCu, int offDom,
       float* __restrict__ out)
{
    __shared__ float sW1[4 * 64];
    __shared__ float sb1[64];
    __shared__ float sW2[64 * 64];
    __shared__ float sb2[64];
    __shared__ float sW3[64];
    __shared__ float sWa[8];
    __shared__ float sb3s;
    __shared__ float sH1[32 * 64];          // layer-1 activations, 32 nodes/block
    __shared__ double sRedN[16], sRedE[16];

    int tid = threadIdx.x;
    int t = blockIdx.x * NT + tid;

    // ---- stage weights into smem (used in Phase B) ----
    for (int i = tid; i < 64 * 64; i += NT) sW2[i] = W2[i];
    for (int i = tid; i < 4 * 64; i += NT) sW1[i] = W1[i];
    if (tid < 64) { sb1[tid] = b1[tid]; sb2[tid] = b2[tid]; sW3[tid] = W3[tid]; }
    if (tid == 0) sb3s = b3[0];
    if (tid < 8) {
        int c = tid & 3, half = tid >> 2;
        float acc = 0.f;
        for (int h = 0; h < 64; h++) acc += gat_W[c * 64 + h] * gat_a[half * 64 + h];
        sWa[tid] = acc;
    }

    // ---- Phase A: per-edge gather + CSR row starts ----
    if (t == 0) { dAccNode = 0.0; dAccEdge = 0.0; dRowStart[N] = E; }
    if (t < E) {
        int r = row[t];
        dJv[t] = J[(size_t)r * (size_t)N + (size_t)col[t]];
        if (t == 0 || row[t - 1] != r) dRowStart[r] = t;
    }
    gridBarrier();

    // ---- Phase B: node features + GAT scalars + Ci MLP (16 threads/node) ----
    int j = t >> 4, s = t & 15;
    int base = 0, deg = 0, e = 0;
    bool valid = false;
    if (j < N) {
        base = ldcgi(&dRowStart[j]);
        deg = ldcgi(&dRowStart[j + 1]) - base;
        valid = (s < deg);
        e = base + s;
    }
    float jv = valid ? dJv[e] : 0.f;   // deg==16 -> e == t, self-written in Phase A
    float js = grpSum16(jv);

    float bv = 0.f, f1 = 0.f, f2 = 0.f;
    float feat0 = 0.f, feat1 = 0.f, feat2 = 0.f, feat3 = 0.f;
    int nodeLocal = tid >> 4, j4 = s * 4;
    if (j < N) {
        bv = bias[j];
        feat0 = -bv; feat1 = bv; feat2 = (float)deg; feat3 = js;
        f1 = feat0 * sWa[0] + feat1 * sWa[1] + feat2 * sWa[2] + feat3 * sWa[3];
        f2 = feat0 * sWa[4] + feat1 * sWa[5] + feat2 * sWa[6] + feat3 * sWa[7];
        if (s == 0) { dF1[j] = f1; dF2[j] = f2; }
#pragma unroll
        for (int n = 0; n < 4; n++) {
            int jj = j4 + n;
            float a = sb1[jj] + feat0 * sW1[jj] + feat1 * sW1[64 + jj]
                    + feat2 * sW1[128 + jj] + feat3 * sW1[192 + jj];
            sH1[nodeLocal * 64 + jj] = fmaxf(a, 0.f);
        }
    }
    __syncwarp();
    float ciPart = 0.f;
    if (j < N) {
        float a0 = sb2[j4], a1 = sb2[j4 + 1], a2 = sb2[j4 + 2], a3 = sb2[j4 + 3];
        const float* hb = &sH1[nodeLocal * 64];
        for (int k2 = 0; k2 < 64; k2++) {
            float h = hb[k2];
            const float* wr = &sW2[k2 * 64 + j4];
            a0 += h * wr[0]; a1 += h * wr[1]; a2 += h * wr[2]; a3 += h * wr[3];
        }
        ciPart = fmaxf(a0, 0.f) * sW3[j4]     + fmaxf(a1, 0.f) * sW3[j4 + 1]
               + fmaxf(a2, 0.f) * sW3[j4 + 2] + fmaxf(a3, 0.f) * sW3[j4 + 3];
    }
    float ci = grpSum16(ciPart) + sb3s;
    if (j < N && s == 0) { dCi[j] = ci; out[offCi + j] = ci; }
    gridBarrier();   // dF1/dF2 visible cross-block

    // ---- Phase C+D: per-edge Cij/aJ + per-node dom, no barrier between ----
    int k = 0, f = 0;
    float aJ = 0.f, Cij = 0.f;
    if (valid) {
        k = col[e]; f = rev[e];
        float e1v = lrelu02(f1 + ldcg1(&dF2[k]));
        float e2v = lrelu02(ldcg1(&dF1[k]) + f2);
        Cij = 0.5f * (expf(e1v) + expf(e2v));
        aJ = jv / Cij;
        dCij[e] = Cij;
        daJ[e] = aJ;
        dEmA[e] = make_float2(0.f, 0.f);
    }
    float csum = grpSum16(Cij);
    float2 bx = make_float2(0.f, 0.f);
    float dinv = 0.f;
    if (j < N) {
        float raw = ci + csum;
        float mag = fmaxf(fabsf(raw), 0.1f);
        float dom = (raw < 0.f) ? -mag : mag;
        dinv = 1.f / dom;
        float bs = bv * dinv;
        bx = make_float2(-bs, bs);
        if (s == 0) {
            out[offDom + j] = dom;
            float m = fmaxf(bx.x, bx.y);
            float ls = m + log1pf(expf(-fabsf(bx.x - bx.y)));
            dHidA[j] = make_float2(bx.x - ls, bx.y - ls);
        }
    }
    int nstep = *nstepPtr;
    gridBarrier();   // dHidA + dEmA visible cross-block

    // ---- Phase E: BP loop (all per-edge constants in registers) ----
    float2* emCur = dEmA;  float2* emNext = dEmB;
    float2* hidCur = dHidA; float2* hidNext = dHidB;
    for (int it = 0; it < nstep; ++it) {
        float2 emn = make_float2(0.f, 0.f);
        if (valid) {
            float2 hk = ldcg2(&hidCur[k]);     // cross-block
            float2 mu = ldcg2(&emCur[e]);      // cross-block (written by rev owner)
            float p = hk.x - mu.x, q = hk.y - mu.y;
            float t0 = fmaxf(p + aJ, q - aJ);
            float t1 = fmaxf(p - aJ, q + aJ);
            float m = fmaxf(t0, t1);
            float ls = m + log1pf(expf(-fabsf(t0 - t1)));
            emn.x = Cij * (t0 - ls);
            emn.y = Cij * (t1 - ls);
            emNext[f] = emn;
        }
        emn.x = grpSum16(emn.x);
        emn.y = grpSum16(emn.y);
        if (valid && s == 0) {
            float u0 = bx.x + emn.x * dinv;
            float u1 = bx.y + emn.y * dinv;
            float m2 = fmaxf(u0, u1);
            float ls2 = m2 + log1pf(expf(-fabsf(u0 - u1)));
            hidNext[j] = make_float2(u0 - ls2, u1 - ls2);
        }
        gridBarrier();
        float2* tmp = emCur; emCur = emNext; emNext = tmp;
        tmp = hidCur; hidCur = hidNext; hidNext = tmp;
    }

    // ---- Phase F: readouts + entropies ----
    double accN = 0.0, accE = 0.0;
    if (t < N) {
        float2 h = ldcg2(&hidCur[t]);
        float r0 = expf(h.x), r1 = expf(h.y);
        out[2 * t] = r0; out[2 * t + 1] = r1;
        float nh = -(r0 * logf(r0 + 1e-16f) + r1 * logf(r1 + 1e-16f));
        accN = (double)(ldcg1(&dCi[t]) * nh);
    }
    if (t < Eu) {
        int eu = u2e[t];
        int fu = rev[eu];
        float Js = ldcg1(&daJ[eu]);
        float2 hc = ldcg2(&hidCur[cu[t]]), hr = ldcg2(&hidCur[ru[t]]);
        float2 me = ldcg2(&emCur[eu]), mf = ldcg2(&emCur[fu]);
        float ti0 = hc.x - me.x, ti1 = hc.y - me.y;
        float tj0 = hr.x - mf.x, tj1 = hr.y - mf.y;
        float s00 =  Js + ti0 + tj0;
        float s01 = -Js + ti1 + tj0;
        float s10 = -Js + ti0 + tj1;
        float s11 =  Js + ti1 + tj1;
        float m = fmaxf(fmaxf(s00, s01), fmaxf(s10, s11));
        float p00 = expf(s00 - m), p01 = expf(s01 - m);
        float p10 = expf(s10 - m), p11 = expf(s11 - m);
        float inv = 1.f / (p00 + p01 + p10 + p11);
        p00 *= inv; p01 *= inv; p10 *= inv; p11 *= inv;
        out[offPw + 4 * t + 0] = p00; out[offPw + 4 * t + 1] = p01;
        out[offPw + 4 * t + 2] = p10; out[offPw + 4 * t + 3] = p11;
        float Cu = ldcg1(&dCij[eu]);
        out[offCu + t] = Cu;
        float eh = -(p00 * logf(p00 + 1e-16f) + p01 * logf(p01 + 1e-16f) +
                     p10 * logf(p10 + 1e-16f) + p11 * logf(p11 + 1e-16f));
        accE = (double)(Cu * eh);
    }
    // block reduction of entropies, 2 atomics per block.
    // First: full-warp reduce (all 32 lanes execute -> legal full mask).
#pragma unroll
    for (int o = 16; o > 0; o >>= 1) {
        accN += __shfl_xor_sync(0xffffffffu, accN, o);
        accE += __shfl_xor_sync(0xffffffffu, accE, o);
    }
    int wid = tid >> 5;
    if ((tid & 31) == 0) { sRedN[wid] = accN; sRedE[wid] = accE; }
    __syncthreads();
    // Final: ALL 32 lanes of warp 0 execute the shuffles (legal full mask).
    if (tid < 32) {
        double aN = (tid < 16) ? sRedN[tid] : 0.0;
        double aE = (tid < 16) ? sRedE[tid] : 0.0;
#pragma unroll
        for (int o = 16; o > 0; o >>= 1) {
            aN += __shfl_xor_sync(0xffffffffu, aN, o);
            aE += __shfl_xor_sync(0xffffffffu, aE, o);
        }
        if (tid == 0) {
            atomicAdd(&dAccNode, aN);
            atomicAdd(&dAccEdge, aE);
        }
    }
    gridBarrier();
    if (t == 0) {
        double aN = ldcgd(&dAccNode);
        double aE = ldcgd(&dAccEdge);
        out[offSc + 0] = (float)(aN + aE);
        out[offSc + 1] = (float)aN;
        out[offSc + 2] = (float)aE;
    }
}

// ------------------------------------------------------------------
extern "C" void kernel_launch(void* const* d_in, const int* in_sizes, int n_in,
                              void* d_out, int out_size) {
    const float* J     = (const float*)d_in[0];
    const float* bias  = (const float*)d_in[1];
    const float* gat_W = (const float*)d_in[2];
    const float* gat_a = (const float*)d_in[3];
    const float* W1    = (const float*)d_in[4];
    const float* b1    = (const float*)d_in[5];
    const float* W2    = (const float*)d_in[6];
    const float* b2    = (const float*)d_in[7];
    const float* W3    = (const float*)d_in[8];
    const float* b3    = (const float*)d_in[9];
    const int*   row   = (const int*)d_in[10];
    const int*   col   = (const int*)d_in[11];
    const int*   rev   = (const int*)d_in[12];
    const int*   ru    = (const int*)d_in[13];
    const int*   cu    = (const int*)d_in[14];
    const int*   u2e   = (const int*)d_in[15];
    const int*   nstep = (const int*)d_in[16];
    (void)n_in; (void)out_size;

    int N  = in_sizes[1];
    int E  = in_sizes[10];
    int Eu = in_sizes[13];

    float* out = (float*)d_out;
    int offPw  = 2 * N;
    int offSc  = offPw + 4 * Eu;
    int offCi  = offSc + 3;
    int offCu  = offCi + N;
    int offDom = offCu + Eu;

    kFused<<<NB, NT>>>(J, bias, gat_W, gat_a, W1, b1, W2, b2, W3, b3,
                       row, col, rev, ru, cu, u2e, nstep,
                       N, E, Eu, offPw, offSc, offCi, offCu, offDom, out);
}

// round 7
// speedup vs baseline: 2.4266x; 1.1245x over previous
#include <cuda_runtime.h>

// BPGNN fully fused, degree-16 fast path: e == t, row[t] == t>>4.
// N=4096 nodes, E=65536 directed edges, Eu=32768, HID=64.
// One persistent kernel; 12 grid barriers + tail done-counter.

#define MAXN 4096
#define MAXE 65536
#define NB 128
#define NT 512

__device__ float  dCij[MAXE];
__device__ float  daJ[MAXE];
__device__ float  dF1[MAXN], dF2[MAXN], dCi[MAXN];
__device__ float2 dEmA[MAXE], dEmB[MAXE];
__device__ float2 dHidA[MAXN], dHidB[MAXN];
__device__ double dAccNode, dAccEdge;
__device__ unsigned gBarCount;
__device__ volatile unsigned gBarGen;
__device__ volatile unsigned gDone;

__device__ __forceinline__ float lrelu02(float x) { return x < 0.f ? 0.2f * x : x; }
__device__ __forceinline__ float2 ldcg2(const float2* p) { return __ldcg(p); }
__device__ __forceinline__ float  ldcg1(const float* p)  { return __ldcg(p); }

// CG-style grid barrier: fences only on thread 0 (cumulativity via bar.sync).
__device__ __forceinline__ void gridBarrier() {
    __syncthreads();
    if (threadIdx.x == 0) {
        __threadfence();                       // release (block's writes observed via bar)
        unsigned gen = gBarGen;
        if (atomicAdd(&gBarCount, 1u) == NB - 1u) {
            gBarCount = 0u;
            __threadfence();
            gBarGen = gen + 1u;
        } else {
            while (gBarGen == gen) { }
        }
        __threadfence();                       // acquire
    }
    __syncthreads();
}

__device__ __forceinline__ float grpSum16(float v) {
#pragma unroll
    for (int o = 8; o > 0; o >>= 1) v += __shfl_xor_sync(0xffffffffu, v, o);
    return v;
}

__global__ void __launch_bounds__(NT, 1)
kFused(const float* __restrict__ J, const float* __restrict__ bias,
       const float* __restrict__ gat_W, const float* __restrict__ gat_a,
       const float* __restrict__ W1, const float* __restrict__ b1,
       const float* __restrict__ W2, const float* __restrict__ b2,
       const float* __restrict__ W3, const float* __restrict__ b3,
       const int* __restrict__ col, const int* __restrict__ rev,
       const int* __restrict__ ru, const int* __restrict__ cu,
       const int* __restrict__ u2e, const int* __restrict__ nstepPtr,
       int N, int Eu,
       int offPw, int offSc, int offCi, int offCu, int offDom,
       float* __restrict__ out)
{
    __shared__ float sW1[4 * 64];
    __shared__ float sb1[64];
    __shared__ float sW2[64 * 64];
    __shared__ float sb2[64];
    __shared__ float sW3[64];
    __shared__ float sWa[8];
    __shared__ float sb3s;
    __shared__ float sH1[32 * 64];          // layer-1 activations, 32 nodes/block
    __shared__ double sRedN[16], sRedE[16];

    int tid = threadIdx.x;
    int t = blockIdx.x * NT + tid;
    int j = t >> 4, s = t & 15;            // node j, edge slot s; edge index e == t
    int nstep = __ldg(nstepPtr);

    // ---- stage weights into smem ----
    for (int i = tid; i < 64 * 64; i += NT) sW2[i] = W2[i];
    for (int i = tid; i < 4 * 64; i += NT) sW1[i] = W1[i];
    if (tid < 64) { sb1[tid] = b1[tid]; sb2[tid] = b2[tid]; sW3[tid] = W3[tid]; }
    if (tid == 0) sb3s = b3[0];
    if (tid < 8) {
        int c = tid & 3, half = tid >> 2;
        float acc = 0.f;
        for (int h = 0; h < 64; h++) acc += gat_W[c * 64 + h] * gat_a[half * 64 + h];
        sWa[tid] = acc;
    }
    if (t == 0) { dAccNode = 0.0; dAccEdge = 0.0; gDone = 0u; }

    // ---- Phase A+B (no barrier between): J gather + features + GAT + Ci MLP ----
    int k = __ldg(&col[t]);                 // neighbor
    int f = __ldg(&rev[t]);                 // reverse edge index
    float jv = __ldg(&J[(size_t)j * (size_t)N + (size_t)k]);
    float js = grpSum16(jv);                // row-sum of J for node j (16 lanes)
    float bv = __ldg(&bias[j]);

    __syncthreads();                        // weights staged
    float feat0 = -bv, feat1 = bv, feat2 = 16.f, feat3 = js;
    float f1 = feat0 * sWa[0] + feat1 * sWa[1] + feat2 * sWa[2] + feat3 * sWa[3];
    float f2 = feat0 * sWa[4] + feat1 * sWa[5] + feat2 * sWa[6] + feat3 * sWa[7];
    if (s == 0) { dF1[j] = f1; dF2[j] = f2; }

    int nodeLocal = tid >> 4, j4 = s * 4;
#pragma unroll
    for (int n = 0; n < 4; n++) {
        int jj = j4 + n;
        float a = sb1[jj] + feat0 * sW1[jj] + feat1 * sW1[64 + jj]
                + feat2 * sW1[128 + jj] + feat3 * sW1[192 + jj];
        sH1[nodeLocal * 64 + jj] = fmaxf(a, 0.f);
    }
    __syncwarp();
    float a0 = sb2[j4], a1 = sb2[j4 + 1], a2 = sb2[j4 + 2], a3 = sb2[j4 + 3];
    {
        const float* hb = &sH1[nodeLocal * 64];
        for (int k2 = 0; k2 < 64; k2++) {
            float h = hb[k2];
            const float* wr = &sW2[k2 * 64 + j4];
            a0 += h * wr[0]; a1 += h * wr[1]; a2 += h * wr[2]; a3 += h * wr[3];
        }
    }
    float ciPart = fmaxf(a0, 0.f) * sW3[j4]     + fmaxf(a1, 0.f) * sW3[j4 + 1]
                 + fmaxf(a2, 0.f) * sW3[j4 + 2] + fmaxf(a3, 0.f) * sW3[j4 + 3];
    float ci = grpSum16(ciPart) + sb3s;
    if (s == 0) { dCi[j] = ci; out[offCi + j] = ci; }
    gridBarrier();                          // dF1/dF2 visible cross-block

    // ---- Phase C+D: Cij/aJ per edge, dom per node ----
    float e1v = lrelu02(f1 + ldcg1(&dF2[k]));
    float e2v = lrelu02(ldcg1(&dF1[k]) + f2);
    float Cij = 0.5f * (__expf(e1v) + __expf(e2v));
    float aJ = jv / Cij;
    dCij[t] = Cij;
    daJ[t] = aJ;
    dEmA[t] = make_float2(0.f, 0.f);

    float csum = grpSum16(Cij);
    float raw = ci + csum;
    float mag = fmaxf(fabsf(raw), 0.1f);
    float dom = (raw < 0.f) ? -mag : mag;
    float dinv = 1.f / dom;
    float bs = bv * dinv;
    float2 bx = make_float2(-bs, bs);
    if (s == 0) {
        out[offDom + j] = dom;
        float m = fmaxf(bx.x, bx.y);
        float ls = m + __logf(1.f + __expf(-fabsf(bx.x - bx.y)));
        dHidA[j] = make_float2(bx.x - ls, bx.y - ls);
    }
    gridBarrier();                          // dHidA + dEmA visible

    // ---- Phase E: BP loop ----
    float2* emCur = dEmA;  float2* emNext = dEmB;
    float2* hidCur = dHidA; float2* hidNext = dHidB;
    for (int it = 0; it < nstep; ++it) {
        float2 hk = ldcg2(&hidCur[k]);
        float2 mu = ldcg2(&emCur[t]);
        float p = hk.x - mu.x, q = hk.y - mu.y;
        float t0 = fmaxf(p + aJ, q - aJ);
        float t1 = fmaxf(p - aJ, q + aJ);
        float m = fmaxf(t0, t1);
        float ls = m + __logf(1.f + __expf(-fabsf(t0 - t1)));
        float2 emn = make_float2(Cij * (t0 - ls), Cij * (t1 - ls));
        emNext[f] = emn;
        emn.x = grpSum16(emn.x);
        emn.y = grpSum16(emn.y);
        if (s == 0) {
            float u0 = bx.x + emn.x * dinv;
            float u1 = bx.y + emn.y * dinv;
            float m2 = fmaxf(u0, u1);
            float ls2 = m2 + __logf(1.f + __expf(-fabsf(u0 - u1)));
            hidNext[j] = make_float2(u0 - ls2, u1 - ls2);
        }
        gridBarrier();
        float2* tmp = emCur; emCur = emNext; emNext = tmp;
        tmp = hidCur; hidCur = hidNext; hidNext = tmp;
    }

    // ---- Phase F: readouts + entropies ----
    double accN = 0.0, accE = 0.0;
    if (t < N) {
        float2 h = ldcg2(&hidCur[t]);
        float r0 = __expf(h.x), r1 = __expf(h.y);
        out[2 * t] = r0; out[2 * t + 1] = r1;
        float nh = -(r0 * __logf(r0 + 1e-16f) + r1 * __logf(r1 + 1e-16f));
        accN = (double)(ldcg1(&dCi[t]) * nh);
    }
    if (t < Eu) {
        int eu = __ldg(&u2e[t]);
        int fu = __ldg(&rev[eu]);
        float Js = ldcg1(&daJ[eu]);
        float2 hc = ldcg2(&hidCur[__ldg(&cu[t])]);
        float2 hr = ldcg2(&hidCur[__ldg(&ru[t])]);
        float2 me = ldcg2(&emCur[eu]), mf = ldcg2(&emCur[fu]);
        float ti0 = hc.x - me.x, ti1 = hc.y - me.y;
        float tj0 = hr.x - mf.x, tj1 = hr.y - mf.y;
        float s00 =  Js + ti0 + tj0;
        float s01 = -Js + ti1 + tj0;
        float s10 = -Js + ti0 + tj1;
        float s11 =  Js + ti1 + tj1;
        float m = fmaxf(fmaxf(s00, s01), fmaxf(s10, s11));
        float p00 = __expf(s00 - m), p01 = __expf(s01 - m);
        float p10 = __expf(s10 - m), p11 = __expf(s11 - m);
        float inv = 1.f / (p00 + p01 + p10 + p11);
        p00 *= inv; p01 *= inv; p10 *= inv; p11 *= inv;
        out[offPw + 4 * t + 0] = p00; out[offPw + 4 * t + 1] = p01;
        out[offPw + 4 * t + 2] = p10; out[offPw + 4 * t + 3] = p11;
        float Cu = ldcg1(&dCij[eu]);
        out[offCu + t] = Cu;
        float eh = -(p00 * __logf(p00 + 1e-16f) + p01 * __logf(p01 + 1e-16f) +
                     p10 * __logf(p10 + 1e-16f) + p11 * __logf(p11 + 1e-16f));
        accE = (double)(Cu * eh);
    }
    // block reduction (full-warp masks everywhere), 2 atomics/block
#pragma unroll
    for (int o = 16; o > 0; o >>= 1) {
        accN += __shfl_xor_sync(0xffffffffu, accN, o);
        accE += __shfl_xor_sync(0xffffffffu, accE, o);
    }
    int wid = tid >> 5;
    if ((tid & 31) == 0) { sRedN[wid] = accN; sRedE[wid] = accE; }
    __syncthreads();
    if (tid < 32) {
        double aN = (tid < 16) ? sRedN[tid] : 0.0;
        double aE = (tid < 16) ? sRedE[tid] : 0.0;
#pragma unroll
        for (int o = 16; o > 0; o >>= 1) {
            aN += __shfl_xor_sync(0xffffffffu, aN, o);
            aE += __shfl_xor_sync(0xffffffffu, aE, o);
        }
        if (tid == 0) {
            atomicAdd(&dAccNode, aN);
            atomicAdd(&dAccEdge, aE);
            __threadfence();
            atomicAdd((unsigned*)&gDone, 1u);
        }
    }
    // only block 0's thread 0 waits for all contributions, writes scalars
    if (t == 0) {
        while (gDone < NB) { }
        __threadfence();
        double aN = *((volatile double*)&dAccNode);
        double aE = *((volatile double*)&dAccEdge);
        out[offSc + 0] = (float)(aN + aE);
        out[offSc + 1] = (float)aN;
        out[offSc + 2] = (float)aE;
    }
}

// ------------------------------------------------------------------
extern "C" void kernel_launch(void* const* d_in, const int* in_sizes, int n_in,
                              void* d_out, int out_size) {
    const float* J     = (const float*)d_in[0];
    const float* bias  = (const float*)d_in[1];
    const float* gat_W = (const float*)d_in[2];
    const float* gat_a = (const float*)d_in[3];
    const float* W1    = (const float*)d_in[4];
    const float* b1    = (const float*)d_in[5];
    const float* W2    = (const float*)d_in[6];
    const float* b2    = (const float*)d_in[7];
    const float* W3    = (const float*)d_in[8];
    const float* b3    = (const float*)d_in[9];
    const int*   col   = (const int*)d_in[11];
    const int*   rev   = (const int*)d_in[12];
    const int*   ru    = (const int*)d_in[13];
    const int*   cu    = (const int*)d_in[14];
    const int*   u2e   = (const int*)d_in[15];
    const int*   nstep = (const int*)d_in[16];
    (void)n_in; (void)out_size;

    int N  = in_sizes[1];
    int Eu = in_sizes[13];

    float* out = (float*)d_out;
    int offPw  = 2 * N;
    int offSc  = offPw + 4 * Eu;
    int offCi  = offSc + 3;
    int offCu  = offCi + N;
    int offDom = offCu + Eu;

    kFused<<<NB, NT>>>(J, bias, gat_W, gat_a, W1, b1, W2, b2, W3, b3,
                       col, rev, ru, cu, u2e, nstep,
                       N, Eu, offPw, offSc, offCi, offCu, offDom, out);
}

// round 8
// speedup vs baseline: 2.6551x; 1.0942x over previous
#include <cuda_runtime.h>

// BPGNN fully fused, degree-16 circulant fast path: edge index == thread index.
// N=4096, E=65536, Eu=32768, HID=64. One persistent kernel.
// BP loop uses NEIGHBOR-LOCAL syncs (deps span <= +-7 blocks on the 128-ring),
// one global barrier before the (globally-indexed) pairwise readout.

#define MAXN 4096
#define MAXE 65536
#define NB 128
#define NT 512
#define NBR 7          // ring distance: ceil(193/32)

__device__ float  dCij[MAXE];
__device__ float  daJ[MAXE];
__device__ float  dF1[MAXN], dF2[MAXN], dCi[MAXN];
__device__ float2 dEmA[MAXE], dEmB[MAXE];
__device__ float2 dHidA[MAXN], dHidB[MAXN];
__device__ double dAccNode, dAccEdge;
__device__ unsigned gBarCount;
__device__ volatile unsigned gBarGen;
__device__ volatile unsigned gDone;
__device__ volatile int gProg[NB * 32];    // one 128B line per block; reset to 0 at end

__device__ __forceinline__ float lrelu02(float x) { return x < 0.f ? 0.2f * x : x; }
__device__ __forceinline__ float2 ldcg2(const float2* p) { return __ldcg(p); }
__device__ __forceinline__ float  ldcg1(const float* p)  { return __ldcg(p); }

// neighbor-local sync: publish own progress, wait for the 14 ring neighbors.
__device__ __forceinline__ void nbrSync(int bid, int val) {
    __syncthreads();                       // block's stores complete
    int tid = threadIdx.x;
    if (tid == 0) {                        // arrival (store issues before polls below:
        __threadfence();                   //  sequential ifs, same warp, program order)
        gProg[bid * 32] = val;
    }
    if (tid >= 1 && tid <= 2 * NBR) {      // 14 pollers, one neighbor each
        int d = (tid <= NBR) ? tid : -(tid - NBR);
        int nb = (bid + d + NB) & (NB - 1);
        while (gProg[nb * 32] < val) { }
        __threadfence();                   // acquire
    }
    __syncthreads();
}

// global barrier (used once, before globally-indexed Phase F)
__device__ __forceinline__ void gridBarrier() {
    __syncthreads();
    if (threadIdx.x == 0) {
        __threadfence();
        unsigned gen = gBarGen;
        if (atomicAdd(&gBarCount, 1u) == NB - 1u) {
            gBarCount = 0u;
            __threadfence();
            gBarGen = gen + 1u;
        } else {
            while (gBarGen == gen) { }
        }
        __threadfence();
    }
    __syncthreads();
}

__device__ __forceinline__ float grpSum16(float v) {
#pragma unroll
    for (int o = 8; o > 0; o >>= 1) v += __shfl_xor_sync(0xffffffffu, v, o);
    return v;
}

__global__ void __launch_bounds__(NT, 1)
kFused(const float* __restrict__ J, const float* __restrict__ bias,
       const float* __restrict__ gat_W, const float* __restrict__ gat_a,
       const float* __restrict__ W1, const float* __restrict__ b1,
       const float* __restrict__ W2, const float* __restrict__ b2,
       const float* __restrict__ W3, const float* __restrict__ b3,
       const int* __restrict__ col, const int* __restrict__ rev,
       const int* __restrict__ ru, const int* __restrict__ cu,
       const int* __restrict__ u2e, const int* __restrict__ nstepPtr,
       int N, int Eu,
       int offPw, int offSc, int offCi, int offCu, int offDom,
       float* __restrict__ out)
{
    __shared__ float sW1[4 * 64];
    __shared__ float sb1[64];
    __shared__ float sW2[64 * 64];
    __shared__ float sb2[64];
    __shared__ float sW3[64];
    __shared__ float sWa[8];
    __shared__ float sb3s;
    __shared__ float sH1[32 * 64];
    __shared__ double sRedN[16], sRedE[16];

    int tid = threadIdx.x;
    int bid = blockIdx.x;
    int t = bid * NT + tid;
    int j = t >> 4, s = t & 15;            // node j, slot s; edge index == t
    int nstep = __ldg(nstepPtr);

    // ---- stage weights ----
    for (int i = tid; i < 64 * 64; i += NT) sW2[i] = W2[i];
    for (int i = tid; i < 4 * 64; i += NT) sW1[i] = W1[i];
    if (tid < 64) { sb1[tid] = b1[tid]; sb2[tid] = b2[tid]; sW3[tid] = W3[tid]; }
    if (tid == 0) sb3s = b3[0];
    if (tid < 8) {
        int c = tid & 3, half = tid >> 2;
        float acc = 0.f;
        for (int h = 0; h < 64; h++) acc += gat_W[c * 64 + h] * gat_a[half * 64 + h];
        sWa[tid] = acc;
    }
    if (t == 0) { dAccNode = 0.0; dAccEdge = 0.0; gDone = 0u; }

    // ---- Phase A+B: J gather + features + GAT scalars + Ci MLP ----
    int k = __ldg(&col[t]);
    int f = __ldg(&rev[t]);
    float jv = __ldg(&J[(size_t)j * (size_t)N + (size_t)k]);
    float js = grpSum16(jv);
    float bv = __ldg(&bias[j]);

    // prefetch Phase-F index chains (constant; hides dependent-load tail later)
    int eu = 0, fu = 0, icu = 0, iru = 0;
    if (t < Eu) {
        eu = __ldg(&u2e[t]); fu = __ldg(&rev[eu]);
        icu = __ldg(&cu[t]); iru = __ldg(&ru[t]);
    }

    __syncthreads();
    float feat0 = -bv, feat1 = bv, feat2 = 16.f, feat3 = js;
    float f1 = feat0 * sWa[0] + feat1 * sWa[1] + feat2 * sWa[2] + feat3 * sWa[3];
    float f2 = feat0 * sWa[4] + feat1 * sWa[5] + feat2 * sWa[6] + feat3 * sWa[7];
    if (s == 0) { dF1[j] = f1; dF2[j] = f2; }

    int nodeLocal = tid >> 4, j4 = s * 4;
#pragma unroll
    for (int n = 0; n < 4; n++) {
        int jj = j4 + n;
        float a = sb1[jj] + feat0 * sW1[jj] + feat1 * sW1[64 + jj]
                + feat2 * sW1[128 + jj] + feat3 * sW1[192 + jj];
        sH1[nodeLocal * 64 + jj] = fmaxf(a, 0.f);
    }
    __syncwarp();
    float a0 = sb2[j4], a1 = sb2[j4 + 1], a2 = sb2[j4 + 2], a3 = sb2[j4 + 3];
    {
        const float* hb = &sH1[nodeLocal * 64];
        for (int k2 = 0; k2 < 64; k2++) {
            float h = hb[k2];
            const float* wr = &sW2[k2 * 64 + j4];
            a0 += h * wr[0]; a1 += h * wr[1]; a2 += h * wr[2]; a3 += h * wr[3];
        }
    }
    float ciPart = fmaxf(a0, 0.f) * sW3[j4]     + fmaxf(a1, 0.f) * sW3[j4 + 1]
                 + fmaxf(a2, 0.f) * sW3[j4 + 2] + fmaxf(a3, 0.f) * sW3[j4 + 3];
    float ci = grpSum16(ciPart) + sb3s;
    if (s == 0) { dCi[j] = ci; out[offCi + j] = ci; }
    nbrSync(bid, 1);                        // dF1/dF2[k] within +-7 blocks

    // ---- Phase C+D: Cij/aJ per edge, dom per node ----
    float e1v = lrelu02(f1 + ldcg1(&dF2[k]));
    float e2v = lrelu02(ldcg1(&dF1[k]) + f2);
    float Cij = 0.5f * (__expf(e1v) + __expf(e2v));
    float aJ = jv / Cij;
    dCij[t] = Cij;
    daJ[t] = aJ;
    dEmA[t] = make_float2(0.f, 0.f);        // for Phase F if nstep even

    float csum = grpSum16(Cij);
    float raw = ci + csum;
    float mag = fmaxf(fabsf(raw), 0.1f);
    float dom = (raw < 0.f) ? -mag : mag;
    float dinv = 1.f / dom;
    float bs = bv * dinv;
    float2 bx = make_float2(-bs, bs);
    if (s == 0) {
        out[offDom + j] = dom;
        float m = fmaxf(bx.x, bx.y);
        float ls = m + __logf(1.f + __expf(-fabsf(bx.x - bx.y)));
        dHidA[j] = make_float2(bx.x - ls, bx.y - ls);
    }
    nbrSync(bid, 2);                        // dHidA[k] within +-7 blocks

    // ---- Phase E: BP loop, neighbor-local sync per iteration ----
    float2* emCur = dEmA;  float2* emNext = dEmB;
    float2* hidCur = dHidA; float2* hidNext = dHidB;
    for (int it = 0; it < nstep; ++it) {
        float2 hk = ldcg2(&hidCur[k]);
        float2 mu = make_float2(0.f, 0.f);
        if (it > 0) mu = ldcg2(&emCur[t]);  // iter 0: messages are exactly zero
        float p = hk.x - mu.x, q = hk.y - mu.y;
        float t0 = fmaxf(p + aJ, q - aJ);
        float t1 = fmaxf(p - aJ, q + aJ);
        float m = fmaxf(t0, t1);
        float ls = m + __logf(1.f + __expf(-fabsf(t0 - t1)));
        float2 emn = make_float2(Cij * (t0 - ls), Cij * (t1 - ls));
        emNext[f] = emn;
        emn.x = grpSum16(emn.x);
        emn.y = grpSum16(emn.y);
        if (s == 0) {
            float u0 = bx.x + emn.x * dinv;
            float u1 = bx.y + emn.y * dinv;
            float m2 = fmaxf(u0, u1);
            float ls2 = m2 + __logf(1.f + __expf(-fabsf(u0 - u1)));
            hidNext[j] = make_float2(u0 - ls2, u1 - ls2);
        }
        if (it + 1 < nstep) nbrSync(bid, 3 + it);   // last iter covered by gridBarrier
        float2* tmp = emCur; emCur = emNext; emNext = tmp;
        tmp = hidCur; hidCur = hidNext; hidNext = tmp;
    }
    gridBarrier();                          // Phase F has global index patterns

    // ---- Phase F: readouts + entropies ----
    double accN = 0.0, accE = 0.0;
    if (t < N) {
        float2 h = ldcg2(&hidCur[t]);
        float r0 = __expf(h.x), r1 = __expf(h.y);
        out[2 * t] = r0; out[2 * t + 1] = r1;
        float nh = -(r0 * __logf(r0 + 1e-16f) + r1 * __logf(r1 + 1e-16f));
        accN = (double)(ldcg1(&dCi[t]) * nh);
    }
    if (t < Eu) {
        float Js = ldcg1(&daJ[eu]);
        float2 hc = ldcg2(&hidCur[icu]);
        float2 hr = ldcg2(&hidCur[iru]);
        float2 me = ldcg2(&emCur[eu]), mf = ldcg2(&emCur[fu]);
        float ti0 = hc.x - me.x, ti1 = hc.y - me.y;
        float tj0 = hr.x - mf.x, tj1 = hr.y - mf.y;
        float s00 =  Js + ti0 + tj0;
        float s01 = -Js + ti1 + tj0;
        float s10 = -Js + ti0 + tj1;
        float s11 =  Js + ti1 + tj1;
        float m = fmaxf(fmaxf(s00, s01), fmaxf(s10, s11));
        float p00 = __expf(s00 - m), p01 = __expf(s01 - m);
        float p10 = __expf(s10 - m), p11 = __expf(s11 - m);
        float inv = 1.f / (p00 + p01 + p10 + p11);
        p00 *= inv; p01 *= inv; p10 *= inv; p11 *= inv;
        out[offPw + 4 * t + 0] = p00; out[offPw + 4 * t + 1] = p01;
        out[offPw + 4 * t + 2] = p10; out[offPw + 4 * t + 3] = p11;
        float Cu = ldcg1(&dCij[eu]);
        out[offCu + t] = Cu;
        float eh = -(p00 * __logf(p00 + 1e-16f) + p01 * __logf(p01 + 1e-16f) +
                     p10 * __logf(p10 + 1e-16f) + p11 * __logf(p11 + 1e-16f));
        accE = (double)(Cu * eh);
    }
    // reset own progress counter for the next graph replay (nobody polls after
    // the global barrier above)
    if (tid == 0) gProg[bid * 32] = 0;

    // block entropy reduction (full-warp masks), 2 atomics/block
#pragma unroll
    for (int o = 16; o > 0; o >>= 1) {
        accN += __shfl_xor_sync(0xffffffffu, accN, o);
        accE += __shfl_xor_sync(0xffffffffu, accE, o);
    }
    int wid = tid >> 5;
    if ((tid & 31) == 0) { sRedN[wid] = accN; sRedE[wid] = accE; }
    __syncthreads();
    if (tid < 32) {
        double aN = (tid < 16) ? sRedN[tid] : 0.0;
        double aE = (tid < 16) ? sRedE[tid] : 0.0;
#pragma unroll
        for (int o = 16; o > 0; o >>= 1) {
            aN += __shfl_xor_sync(0xffffffffu, aN, o);
            aE += __shfl_xor_sync(0xffffffffu, aE, o);
        }
        if (tid == 0) {
            atomicAdd(&dAccNode, aN);
            atomicAdd(&dAccEdge, aE);
            __threadfence();
            atomicAdd((unsigned*)&gDone, 1u);
        }
    }
    if (t == 0) {
        while (gDone < NB) { }
        __threadfence();
        double aN = *((volatile double*)&dAccNode);
        double aE = *((volatile double*)&dAccEdge);
        out[offSc + 0] = (float)(aN + aE);
        out[offSc + 1] = (float)aN;
        out[offSc + 2] = (float)aE;
    }
}

// ------------------------------------------------------------------
extern "C" void kernel_launch(void* const* d_in, const int* in_sizes, int n_in,
                              void* d_out, int out_size) {
    const float* J     = (const float*)d_in[0];
    const float* bias  = (const float*)d_in[1];
    const float* gat_W = (const float*)d_in[2];
    const float* gat_a = (const float*)d_in[3];
    const float* W1    = (const float*)d_in[4];
    const float* b1    = (const float*)d_in[5];
    const float* W2    = (const float*)d_in[6];
    const float* b2    = (const float*)d_in[7];
    const float* W3    = (const float*)d_in[8];
    const float* b3    = (const float*)d_in[9];
    const int*   col   = (const int*)d_in[11];
    const int*   rev   = (const int*)d_in[12];
    const int*   ru    = (const int*)d_in[13];
    const int*   cu    = (const int*)d_in[14];
    const int*   u2e   = (const int*)d_in[15];
    const int*   nstep = (const int*)d_in[16];
    (void)n_in; (void)out_size;

    int N  = in_sizes[1];
    int Eu = in_sizes[13];

    float* out = (float*)d_out;
    int offPw  = 2 * N;
    int offSc  = offPw + 4 * Eu;
    int offCi  = offSc + 3;
    int offCu  = offCi + N;
    int offDom = offCu + Eu;

    kFused<<<NB, NT>>>(J, bias, gat_W, gat_a, W1, b1, W2, b2, W3, b3,
                       col, rev, ru, cu, u2e, nstep,
                       N, Eu, offPw, offSc, offCi, offCu, offDom, out);
}